// round 16
// baseline (speedup 1.0000x reference)
#include <cuda_runtime.h>
#include <cstdint>
#include <cstdio>

#define NMAX 50000
#define EMAX 600000
#define CDIV(a,b) (((a)+(b)-1)/(b))

// ---------------- scratch (device globals; no allocation allowed) ----------------
__device__ __align__(16) float d_hg  [(size_t)NMAX*64];   // GCN gemm out
__device__ __align__(16) float d_g1  [(size_t)NMAX*64];
__device__ __align__(16) float d_g2  [(size_t)NMAX*64];
__device__ __align__(16) float d_hgat[(size_t)NMAX*256];  // GAT gemm out
__device__ __align__(16) float d_a1  [(size_t)NMAX*256];
__device__ __align__(16) float d_a2  [(size_t)NMAX*64];
__device__ __align__(16) float d_hsl [(size_t)NMAX*64];   // SAGE x@Wl
__device__ __align__(16) float d_hsr [(size_t)NMAX*64];   // SAGE x@Wr
__device__ __align__(16) float d_s1  [(size_t)NMAX*64];
__device__ __align__(16) float d_s2  [(size_t)NMAX*64];
__device__ __align__(16) float d_as  [(size_t)NMAX*4];
__device__ __align__(16) float d_ad  [(size_t)NMAX*4];
__device__ float d_dinv[NMAX];
__device__ int   d_cnt [NMAX];
__device__ int   d_rp  [NMAX+1];
__device__ int   d_cur [NMAX];
__device__ int   d_ci  [EMAX];
__device__ float d_bnsum[192];   // 3 branches x 64; zero-init, bn_final re-zeroes
__device__ float d_bnsq [192];
__device__ float d_bnscale[192]; // per-channel affine for head A-load
__device__ float d_bnshift[192];

// ---------------- helpers ----------------
__device__ __forceinline__ float lrelu(float x){ return x > 0.f ? x : 0.2f * x; }
__device__ __forceinline__ float elu(float x){ return x > 0.f ? x : expm1f(x); }

__device__ __forceinline__ uint32_t f2tf32(float f){
    uint32_t u;
    asm("cvt.rna.tf32.f32 %0, %1;" : "=r"(u) : "f"(f));
    return u;
}
__device__ __forceinline__ void mma_tf32(float4& d,
    uint32_t a0, uint32_t a1, uint32_t a2, uint32_t a3,
    uint32_t b0, uint32_t b1)
{
    asm volatile(
        "mma.sync.aligned.m16n8k8.row.col.f32.tf32.tf32.f32 "
        "{%0,%1,%2,%3}, {%4,%5,%6,%7}, {%8,%9}, {%0,%1,%2,%3};"
        : "+f"(d.x), "+f"(d.y), "+f"(d.z), "+f"(d.w)
        : "r"(a0), "r"(a1), "r"(a2), "r"(a3), "r"(b0), "r"(b1));
}

// ---------------- CSR build ----------------
__global__ void izero_k(int* p, int n){
    int i = blockIdx.x*blockDim.x + threadIdx.x;
    if (i < n) p[i] = 0;
}
__global__ void hist_k(const int* __restrict__ dst, int* cnt, int E){
    int i = blockIdx.x*blockDim.x + threadIdx.x;
    if (i < E) atomicAdd(&cnt[dst[i]], 1);
}
// single-block scan: rp[0]=0, rp[i+1]=incl sum; cur[i]=exclusive sum (cursor init)
__global__ void scan_k(const int* __restrict__ cnt, int* rp, int* cur, int n){
    __shared__ int wsum[32];
    __shared__ int carry_s;
    int lane = threadIdx.x & 31, wid = threadIdx.x >> 5;
    if (threadIdx.x == 0){ carry_s = 0; rp[0] = 0; }
    __syncthreads();
    for (int base = 0; base < n; base += 1024){
        int i = base + threadIdx.x;
        int v = (i < n) ? cnt[i] : 0;
        int x = v;
#pragma unroll
        for (int o = 1; o < 32; o <<= 1){
            int t = __shfl_up_sync(0xffffffffu, x, o);
            if (lane >= o) x += t;
        }
        if (lane == 31) wsum[wid] = x;
        __syncthreads();
        if (wid == 0){
            int y = wsum[lane];
#pragma unroll
            for (int o = 1; o < 32; o <<= 1){
                int t = __shfl_up_sync(0xffffffffu, y, o);
                if (lane >= o) y += t;
            }
            wsum[lane] = y;
        }
        __syncthreads();
        int incl = x + (wid > 0 ? wsum[wid-1] : 0) + carry_s;
        if (i < n){ rp[i+1] = incl; cur[i] = incl - v; }
        __syncthreads();
        if (threadIdx.x == 1023) carry_s = incl;
        __syncthreads();
    }
}
__global__ void csr_fill_k(const int* __restrict__ src, const int* __restrict__ dst,
                           int* cursor, int* ci, int E){
    int e = blockIdx.x*blockDim.x + threadIdx.x;
    if (e < E){
        int p = atomicAdd(&cursor[dst[e]], 1);
        ci[p] = src[e];
    }
}
__global__ void dinv_k(const int* __restrict__ cnt, float* dinv, int n){
    int i = blockIdx.x*blockDim.x + threadIdx.x;
    if (i < n) dinv[i] = rsqrtf((float)cnt[i] + 1.0f);  // +1 self-loop
}

// ---------------- tf32 tensor-core GEMM ----------------
// C[M,F] = A[M,K] @ B[K,F] (+bias)(+relu); K%32==0, F%64==0
__global__ __launch_bounds__(256) void gemm_mma_k(
    const float* __restrict__ A, const float* __restrict__ B,
    float* __restrict__ C, const float* __restrict__ bias,
    int M, int K, int F, int act)
{
    __shared__ uint32_t As[32][136];
    __shared__ uint32_t Bs[32][72];
    int bm = blockIdx.x * 128;
    int bn = blockIdx.y * 64;
    int tid = threadIdx.x;
    int w = tid >> 5, lane = tid & 31;
    int wm = w & 3, wn = w >> 2;
    int g = lane >> 2, ti = lane & 3;

    float4 acc[2][4];
#pragma unroll
    for (int i=0;i<2;i++)
#pragma unroll
        for (int j=0;j<4;j++) acc[i][j] = make_float4(0.f,0.f,0.f,0.f);

    for (int k0 = 0; k0 < K; k0 += 32){
#pragma unroll
        for (int i=0;i<4;i++){
            int l = tid*4 + i;
            int m = l >> 3, kq = l & 7;
            float4 v = make_float4(0.f,0.f,0.f,0.f);
            if (bm + m < M) v = *(const float4*)&A[(size_t)(bm+m)*K + k0 + kq*4];
            As[kq*4+0][m] = f2tf32(v.x);
            As[kq*4+1][m] = f2tf32(v.y);
            As[kq*4+2][m] = f2tf32(v.z);
            As[kq*4+3][m] = f2tf32(v.w);
        }
#pragma unroll
        for (int i=0;i<2;i++){
            int l = tid*2 + i;
            int kk = l >> 4, nq = l & 15;
            float4 v = *(const float4*)&B[(size_t)(k0+kk)*F + bn + nq*4];
            Bs[kk][nq*4+0] = f2tf32(v.x);
            Bs[kk][nq*4+1] = f2tf32(v.y);
            Bs[kk][nq*4+2] = f2tf32(v.z);
            Bs[kk][nq*4+3] = f2tf32(v.w);
        }
        __syncthreads();
#pragma unroll
        for (int kk = 0; kk < 32; kk += 8){
            uint32_t bf[4][2];
#pragma unroll
            for (int j=0;j<4;j++){
                bf[j][0] = Bs[kk + ti    ][wn*32 + j*8 + g];
                bf[j][1] = Bs[kk + 4 + ti][wn*32 + j*8 + g];
            }
#pragma unroll
            for (int mi=0;mi<2;mi++){
                int mb = wm*32 + mi*16;
                uint32_t a0 = As[kk + ti    ][mb + g];
                uint32_t a1 = As[kk + ti    ][mb + g + 8];
                uint32_t a2 = As[kk + 4 + ti][mb + g];
                uint32_t a3 = As[kk + 4 + ti][mb + g + 8];
#pragma unroll
                for (int j=0;j<4;j++)
                    mma_tf32(acc[mi][j], a0, a1, a2, a3, bf[j][0], bf[j][1]);
            }
        }
        __syncthreads();
    }

#pragma unroll
    for (int mi=0;mi<2;mi++){
#pragma unroll
        for (int j=0;j<4;j++){
            int c = bn + wn*32 + j*8 + 2*ti;
            float b0 = bias ? bias[c]   : 0.f;
            float b1 = bias ? bias[c+1] : 0.f;
            float4 a = acc[mi][j];
            float2 v0 = make_float2(a.x + b0, a.y + b1);
            float2 v1 = make_float2(a.z + b0, a.w + b1);
            if (act){
                v0.x = fmaxf(v0.x, 0.f); v0.y = fmaxf(v0.y, 0.f);
                v1.x = fmaxf(v1.x, 0.f); v1.y = fmaxf(v1.y, 0.f);
            }
            int r0 = bm + wm*32 + mi*16 + g;
            int r1 = r0 + 8;
            if (r0 < M) *(float2*)&C[(size_t)r0*F + c] = v0;
            if (r1 < M) *(float2*)&C[(size_t)r1*F + c] = v1;
        }
    }
}

// fused fc1+fc2 head: out[M,2] = relu(BN(cat)@W1 + b1) @ W2 + b2
// A panel split across 3 stride-64 buffers with per-channel BN affine.
__global__ __launch_bounds__(256) void fc_head_mma_k(
    const float* __restrict__ A0, const float* __restrict__ A1, const float* __restrict__ A2,
    const float* __restrict__ B, float* __restrict__ out,
    const float* __restrict__ bias, const float* __restrict__ w2,
    const float* __restrict__ b2,
    int M, const float* __restrict__ ascale, const float* __restrict__ ashift)
{
    const int K = 192, F = 64;
    __shared__ uint32_t As[32][136];
    __shared__ uint32_t Bs[32][72];
    __shared__ float w2s[128];
    __shared__ float part[128][4];   // [row_local][wn*2 + o]
    int bm = blockIdx.x * 128;
    int tid = threadIdx.x;
    int w = tid >> 5, lane = tid & 31;
    int wm = w & 3, wn = w >> 2;
    int g = lane >> 2, ti = lane & 3;

    if (tid < 128) w2s[tid] = w2[tid];

    float4 acc[2][4];
#pragma unroll
    for (int i=0;i<2;i++)
#pragma unroll
        for (int j=0;j<4;j++) acc[i][j] = make_float4(0.f,0.f,0.f,0.f);

    for (int k0 = 0; k0 < K; k0 += 32){
        const float* Ab = (k0 < 64) ? A0 : ((k0 < 128) ? A1 : A2);
        int cb = k0 & 63;
#pragma unroll
        for (int i=0;i<4;i++){
            int l = tid*4 + i;
            int m = l >> 3, kq = l & 7;
            float4 v = make_float4(0.f,0.f,0.f,0.f);
            if (bm + m < M) v = *(const float4*)&Ab[(size_t)(bm+m)*64 + cb + kq*4];
            int c = k0 + kq*4;
            v.x = v.x*ascale[c]   + ashift[c];
            v.y = v.y*ascale[c+1] + ashift[c+1];
            v.z = v.z*ascale[c+2] + ashift[c+2];
            v.w = v.w*ascale[c+3] + ashift[c+3];
            As[kq*4+0][m] = f2tf32(v.x);
            As[kq*4+1][m] = f2tf32(v.y);
            As[kq*4+2][m] = f2tf32(v.z);
            As[kq*4+3][m] = f2tf32(v.w);
        }
#pragma unroll
        for (int i=0;i<2;i++){
            int l = tid*2 + i;
            int kk = l >> 4, nq = l & 15;
            float4 v = *(const float4*)&B[(size_t)(k0+kk)*F + nq*4];
            Bs[kk][nq*4+0] = f2tf32(v.x);
            Bs[kk][nq*4+1] = f2tf32(v.y);
            Bs[kk][nq*4+2] = f2tf32(v.z);
            Bs[kk][nq*4+3] = f2tf32(v.w);
        }
        __syncthreads();
#pragma unroll
        for (int kk = 0; kk < 32; kk += 8){
            uint32_t bf[4][2];
#pragma unroll
            for (int j=0;j<4;j++){
                bf[j][0] = Bs[kk + ti    ][wn*32 + j*8 + g];
                bf[j][1] = Bs[kk + 4 + ti][wn*32 + j*8 + g];
            }
#pragma unroll
            for (int mi=0;mi<2;mi++){
                int mb = wm*32 + mi*16;
                uint32_t a0 = As[kk + ti    ][mb + g];
                uint32_t a1 = As[kk + ti    ][mb + g + 8];
                uint32_t a2 = As[kk + 4 + ti][mb + g];
                uint32_t a3 = As[kk + 4 + ti][mb + g + 8];
#pragma unroll
                for (int j=0;j<4;j++)
                    mma_tf32(acc[mi][j], a0, a1, a2, a3, bf[j][0], bf[j][1]);
            }
        }
        __syncthreads();
    }

    // epilogue: fc1 bias+relu, then per-thread fc2 partial dot
    float p[2][2][2];   // [mi][half r0/r1][o]
#pragma unroll
    for (int mi=0;mi<2;mi++)
#pragma unroll
        for (int hf=0;hf<2;hf++){ p[mi][hf][0]=0.f; p[mi][hf][1]=0.f; }

#pragma unroll
    for (int mi=0;mi<2;mi++){
#pragma unroll
        for (int j=0;j<4;j++){
            int c = wn*32 + j*8 + 2*ti;
            float b0 = bias[c], b1 = bias[c+1];
            float4 a = acc[mi][j];
            float v00 = fmaxf(a.x + b0, 0.f), v01 = fmaxf(a.y + b1, 0.f);
            float v10 = fmaxf(a.z + b0, 0.f), v11 = fmaxf(a.w + b1, 0.f);
            float wc0o0 = w2s[c*2+0],   wc0o1 = w2s[c*2+1];
            float wc1o0 = w2s[(c+1)*2], wc1o1 = w2s[(c+1)*2+1];
            p[mi][0][0] += v00*wc0o0 + v01*wc1o0;
            p[mi][0][1] += v00*wc0o1 + v01*wc1o1;
            p[mi][1][0] += v10*wc0o0 + v11*wc1o0;
            p[mi][1][1] += v10*wc0o1 + v11*wc1o1;
        }
    }
    // reduce over the 4 ti-lanes (lane = g*4+ti)
#pragma unroll
    for (int mi=0;mi<2;mi++)
#pragma unroll
        for (int hf=0;hf<2;hf++)
#pragma unroll
            for (int o=0;o<2;o++){
                float v = p[mi][hf][o];
                v += __shfl_xor_sync(0xffffffffu, v, 1);
                v += __shfl_xor_sync(0xffffffffu, v, 2);
                p[mi][hf][o] = v;
            }
    if (ti == 0){
#pragma unroll
        for (int mi=0;mi<2;mi++)
#pragma unroll
            for (int hf=0;hf<2;hf++){
                int row = wm*32 + mi*16 + g + hf*8;
                part[row][wn*2+0] = p[mi][hf][0];
                part[row][wn*2+1] = p[mi][hf][1];
            }
    }
    __syncthreads();
    {
        int row = tid >> 1, o = tid & 1;
        int gr = bm + row;
        if (gr < M)
            out[(size_t)gr*2 + o] = part[row][0*2+o] + part[row][1*2+o] + b2[o];
    }
}

// ---------------- fused gather kernels (warp per node, edge-unrolled x2) ----------------
__global__ void gcn_gather_k(const float* __restrict__ h, const float* __restrict__ dinv,
                             const int* __restrict__ rp, const int* __restrict__ ci,
                             const float* __restrict__ bias, float* __restrict__ out, int n)
{
    int w = (blockIdx.x*blockDim.x + threadIdx.x) >> 5;
    if (w >= n) return;
    int lane = threadIdx.x & 31;
    int beg = rp[w], end = rp[w+1];
    float dvd = dinv[w];
    float a0 = dvd * h[(size_t)w*64 + lane];
    float a1 = dvd * h[(size_t)w*64 + 32 + lane];
    int e = beg;
    for (; e + 2 <= end; e += 2){
        int sA = ci[e], sB = ci[e+1];
        float dA = dinv[sA], dB = dinv[sB];
        float hA0 = h[(size_t)sA*64 + lane];
        float hA1 = h[(size_t)sA*64 + 32 + lane];
        float hB0 = h[(size_t)sB*64 + lane];
        float hB1 = h[(size_t)sB*64 + 32 + lane];
        a0 += dA*hA0 + dB*hB0;
        a1 += dA*hA1 + dB*hB1;
    }
    if (e < end){
        int s = ci[e];
        float ds = dinv[s];
        a0 += ds * h[(size_t)s*64 + lane];
        a1 += ds * h[(size_t)s*64 + 32 + lane];
    }
    out[(size_t)w*64 + lane]      = fmaxf(dvd*a0 + bias[lane],    0.f);
    out[(size_t)w*64 + 32 + lane] = fmaxf(dvd*a1 + bias[32+lane], 0.f);
}

__global__ void sage_gather_k(const float* __restrict__ hl, const float* __restrict__ xr,
                              const int* __restrict__ rp, const int* __restrict__ ci,
                              const float* __restrict__ bl, float* __restrict__ out, int n)
{
    int w = (blockIdx.x*blockDim.x + threadIdx.x) >> 5;
    if (w >= n) return;
    int lane = threadIdx.x & 31;
    int beg = rp[w], end = rp[w+1];
    float a0 = 0.f, a1 = 0.f;
    int e = beg;
    for (; e + 2 <= end; e += 2){
        int sA = ci[e], sB = ci[e+1];
        float hA0 = hl[(size_t)sA*64 + lane];
        float hA1 = hl[(size_t)sA*64 + 32 + lane];
        float hB0 = hl[(size_t)sB*64 + lane];
        float hB1 = hl[(size_t)sB*64 + 32 + lane];
        a0 += hA0 + hB0;
        a1 += hA1 + hB1;
    }
    if (e < end){
        int s = ci[e];
        a0 += hl[(size_t)s*64 + lane];
        a1 += hl[(size_t)s*64 + 32 + lane];
    }
    float inv = 1.f / fmaxf((float)(end - beg), 1.f);
    out[(size_t)w*64 + lane]      = fmaxf(a0*inv + bl[lane]    + xr[(size_t)w*64 + lane],      0.f);
    out[(size_t)w*64 + 32 + lane] = fmaxf(a1*inv + bl[32+lane] + xr[(size_t)w*64 + 32 + lane], 0.f);
}

// warp per (node,head), C=64: coalesced h reads + shfl reduce.
// attention vectors staged in smem (H*64 <= 256 floats each).
__global__ __launch_bounds__(256) void gat_scal_w_k(
    const float* __restrict__ h, const float* __restrict__ asrc,
    const float* __restrict__ adst, float* __restrict__ as_, float* __restrict__ ad_,
    int n, int H)
{
    __shared__ float s_as[256], s_ad[256];
    int tid = threadIdx.x;
    int tot = H*64;
    for (int i = tid; i < tot; i += 256){ s_as[i] = asrc[i]; s_ad[i] = adst[i]; }
    __syncthreads();
    int gw = (blockIdx.x*256 + tid) >> 5;   // node*H + head
    if (gw >= n*H) return;
    int lane = tid & 31;
    int node = gw / H, hh = gw - node*H;
    const float* hp = h + (size_t)node*tot + hh*64;
    float v0 = hp[lane], v1 = hp[32+lane];
    float ss = v0*s_as[hh*64+lane] + v1*s_as[hh*64+32+lane];
    float dd = v0*s_ad[hh*64+lane] + v1*s_ad[hh*64+32+lane];
#pragma unroll
    for (int o = 16; o; o >>= 1){
        ss += __shfl_xor_sync(0xffffffffu, ss, o);
        dd += __shfl_xor_sync(0xffffffffu, dd, o);
    }
    if (lane == 0){ as_[gw] = ss; ad_[gw] = dd; }
}

// one-pass online-softmax GAT1 gather (flash-attention rescaling)
__global__ void gat1_gather_k(const float4* __restrict__ h4, const float4* __restrict__ as4,
                              const float4* __restrict__ ad4,
                              const int* __restrict__ rp, const int* __restrict__ ci,
                              const float4* __restrict__ bias4, float4* __restrict__ out4, int n)
{
    int w = (blockIdx.x*blockDim.x + threadIdx.x) >> 5;
    if (w >= n) return;
    int lane = threadIdx.x & 31;
    bool lo = (lane < 16);
    int beg = rp[w], end = rp[w+1];
    float4 ad = ad4[w];
    float adv0 = lo ? ad.x : ad.y;
    float adv1 = lo ? ad.z : ad.w;
    float4 asw = as4[w];
    // init with self-loop: weight exp(es-m)=1
    float m0 = lrelu((lo ? asw.x : asw.y) + adv0);
    float m1 = lrelu((lo ? asw.z : asw.w) + adv1);
    float den0 = 1.f, den1 = 1.f;
    float4 acc0 = h4[(size_t)w*64 + lane];
    float4 acc1 = h4[(size_t)w*64 + 32 + lane];
    int e = beg;
    for (; e + 2 <= end; e += 2){
        int sA = ci[e], sB = ci[e+1];
        float4 aA = as4[sA];
        float4 aB = as4[sB];
        float4 vA0 = h4[(size_t)sA*64 + lane];
        float4 vA1 = h4[(size_t)sA*64 + 32 + lane];
        float4 vB0 = h4[(size_t)sB*64 + lane];
        float4 vB1 = h4[(size_t)sB*64 + 32 + lane];
        // edge A
        {
            float e0 = lrelu((lo ? aA.x : aA.y) + adv0);
            float e1 = lrelu((lo ? aA.z : aA.w) + adv1);
            float mn0 = fmaxf(m0, e0), mn1 = fmaxf(m1, e1);
            float sc0 = expf(m0 - mn0), sc1 = expf(m1 - mn1);
            float we0 = expf(e0 - mn0), we1 = expf(e1 - mn1);
            m0 = mn0; m1 = mn1;
            den0 = den0*sc0 + we0; den1 = den1*sc1 + we1;
            acc0.x = acc0.x*sc0 + we0*vA0.x; acc0.y = acc0.y*sc0 + we0*vA0.y;
            acc0.z = acc0.z*sc0 + we0*vA0.z; acc0.w = acc0.w*sc0 + we0*vA0.w;
            acc1.x = acc1.x*sc1 + we1*vA1.x; acc1.y = acc1.y*sc1 + we1*vA1.y;
            acc1.z = acc1.z*sc1 + we1*vA1.z; acc1.w = acc1.w*sc1 + we1*vA1.w;
        }
        // edge B
        {
            float e0 = lrelu((lo ? aB.x : aB.y) + adv0);
            float e1 = lrelu((lo ? aB.z : aB.w) + adv1);
            float mn0 = fmaxf(m0, e0), mn1 = fmaxf(m1, e1);
            float sc0 = expf(m0 - mn0), sc1 = expf(m1 - mn1);
            float we0 = expf(e0 - mn0), we1 = expf(e1 - mn1);
            m0 = mn0; m1 = mn1;
            den0 = den0*sc0 + we0; den1 = den1*sc1 + we1;
            acc0.x = acc0.x*sc0 + we0*vB0.x; acc0.y = acc0.y*sc0 + we0*vB0.y;
            acc0.z = acc0.z*sc0 + we0*vB0.z; acc0.w = acc0.w*sc0 + we0*vB0.w;
            acc1.x = acc1.x*sc1 + we1*vB1.x; acc1.y = acc1.y*sc1 + we1*vB1.y;
            acc1.z = acc1.z*sc1 + we1*vB1.z; acc1.w = acc1.w*sc1 + we1*vB1.w;
        }
    }
    if (e < end){
        int s = ci[e];
        float4 a = as4[s];
        float4 v0 = h4[(size_t)s*64 + lane];
        float4 v1 = h4[(size_t)s*64 + 32 + lane];
        float e0 = lrelu((lo ? a.x : a.y) + adv0);
        float e1 = lrelu((lo ? a.z : a.w) + adv1);
        float mn0 = fmaxf(m0, e0), mn1 = fmaxf(m1, e1);
        float sc0 = expf(m0 - mn0), sc1 = expf(m1 - mn1);
        float we0 = expf(e0 - mn0), we1 = expf(e1 - mn1);
        den0 = den0*sc0 + we0; den1 = den1*sc1 + we1;
        acc0.x = acc0.x*sc0 + we0*v0.x; acc0.y = acc0.y*sc0 + we0*v0.y;
        acc0.z = acc0.z*sc0 + we0*v0.z; acc0.w = acc0.w*sc0 + we0*v0.w;
        acc1.x = acc1.x*sc1 + we1*v1.x; acc1.y = acc1.y*sc1 + we1*v1.y;
        acc1.z = acc1.z*sc1 + we1*v1.z; acc1.w = acc1.w*sc1 + we1*v1.w;
    }
    float inv0 = 1.f/(den0 + 1e-16f), inv1 = 1.f/(den1 + 1e-16f);
    float4 b0 = bias4[lane], b1 = bias4[32+lane];
    float4 o0, o1;
    o0.x = elu(acc0.x*inv0 + b0.x); o0.y = elu(acc0.y*inv0 + b0.y);
    o0.z = elu(acc0.z*inv0 + b0.z); o0.w = elu(acc0.w*inv0 + b0.w);
    o1.x = elu(acc1.x*inv1 + b1.x); o1.y = elu(acc1.y*inv1 + b1.y);
    o1.z = elu(acc1.z*inv1 + b1.z); o1.w = elu(acc1.w*inv1 + b1.w);
    out4[(size_t)w*64 + lane] = o0;
    out4[(size_t)w*64 + 32 + lane] = o1;
}

// one-pass online-softmax GAT2 gather
__global__ void gat2_gather_k(const float* __restrict__ h, const float* __restrict__ as_,
                              const float* __restrict__ ad_,
                              const int* __restrict__ rp, const int* __restrict__ ci,
                              const float* __restrict__ bias, float* __restrict__ out, int n)
{
    int w = (blockIdx.x*blockDim.x + threadIdx.x) >> 5;
    if (w >= n) return;
    int lane = threadIdx.x & 31;
    int beg = rp[w], end = rp[w+1];
    float adv = ad_[w];
    float m = lrelu(as_[w] + adv);      // self-loop, weight 1
    float den = 1.f;
    float a0 = h[(size_t)w*64 + lane];
    float a1 = h[(size_t)w*64 + 32 + lane];
    int e = beg;
    for (; e + 2 <= end; e += 2){
        int sA = ci[e], sB = ci[e+1];
        float qA = as_[sA], qB = as_[sB];
        float hA0 = h[(size_t)sA*64 + lane];
        float hA1 = h[(size_t)sA*64 + 32 + lane];
        float hB0 = h[(size_t)sB*64 + lane];
        float hB1 = h[(size_t)sB*64 + 32 + lane];
        {
            float ev = lrelu(qA + adv);
            float mn = fmaxf(m, ev);
            float sc = expf(m - mn);
            float we = expf(ev - mn);
            m = mn;
            den = den*sc + we;
            a0 = a0*sc + we*hA0;
            a1 = a1*sc + we*hA1;
        }
        {
            float ev = lrelu(qB + adv);
            float mn = fmaxf(m, ev);
            float sc = expf(m - mn);
            float we = expf(ev - mn);
            m = mn;
            den = den*sc + we;
            a0 = a0*sc + we*hB0;
            a1 = a1*sc + we*hB1;
        }
    }
    if (e < end){
        int s = ci[e];
        float ev = lrelu(as_[s] + adv);
        float hh0 = h[(size_t)s*64 + lane];
        float hh1 = h[(size_t)s*64 + 32 + lane];
        float mn = fmaxf(m, ev);
        float sc = expf(m - mn);
        float we = expf(ev - mn);
        den = den*sc + we;
        a0 = a0*sc + we*hh0;
        a1 = a1*sc + we*hh1;
    }
    float inv = 1.f/(den + 1e-16f);
    out[(size_t)w*64 + lane]      = elu(a0*inv + bias[lane]);
    out[(size_t)w*64 + 32 + lane] = elu(a1*inv + bias[32+lane]);
}

// ---------------- BatchNorm ----------------
__global__ void bn_stats_k(const float* __restrict__ x, float* gsum, float* gsq, int total){
    __shared__ float ss[256];
    __shared__ float sq[256];
    int tid = threadIdx.x;
    float s = 0.f, q = 0.f;
    for (int i = blockIdx.x*256 + tid; i < total; i += gridDim.x*256){
        float v = x[i];
        s += v; q += v*v;
    }
    ss[tid] = s; sq[tid] = q;
    __syncthreads();
    if (tid < 64){
        int c = tid & 63;
        float ts = ss[tid] + ss[tid+64] + ss[tid+128] + ss[tid+192];
        float tq = sq[tid] + sq[tid+64] + sq[tid+128] + sq[tid+192];
        atomicAdd(&gsum[c], ts);
        atomicAdd(&gsq[c], tq);
    }
}
// emits per-channel affine (scale/shift) for the head A-load; re-zeroes accumulators
__global__ void bn_final_k(float* gsum, float* gsq, float* scale, float* shift,
                           const float* __restrict__ g, const float* __restrict__ b, int n){
    int c = threadIdx.x;
    if (c < 64){
        float m = gsum[c] / (float)n;
        float v = gsq[c] / (float)n - m*m;
        float sc = g[c] * rsqrtf(v + 1e-5f);
        scale[c] = sc;
        shift[c] = b[c] - m*sc;
        gsum[c] = 0.f;
        gsq[c]  = 0.f;
    }
}

// ---------------- host orchestration ----------------
static inline float* symf(const void* s){ void* p=nullptr; cudaGetSymbolAddress(&p, s); return (float*)p; }
static inline int*   symi(const void* s){ void* p=nullptr; cudaGetSymbolAddress(&p, s); return (int*)p; }

extern "C" void kernel_launch(void* const* d_in, const int* in_sizes, int n_in,
                              void* d_out, int out_size)
{
    const float* x        = (const float*)d_in[0];
    const int*   eidx     = (const int*)  d_in[1];
    const float* gcn1_w   = (const float*)d_in[2];
    const float* gcn1_b   = (const float*)d_in[3];
    const float* gcn2_w   = (const float*)d_in[4];
    const float* gcn2_b   = (const float*)d_in[5];
    const float* gat1_w   = (const float*)d_in[6];
    const float* gat1_as  = (const float*)d_in[7];
    const float* gat1_ad  = (const float*)d_in[8];
    const float* gat1_b   = (const float*)d_in[9];
    const float* gat2_w   = (const float*)d_in[10];
    const float* gat2_as  = (const float*)d_in[11];
    const float* gat2_ad  = (const float*)d_in[12];
    const float* gat2_b   = (const float*)d_in[13];
    const float* sage1_wl = (const float*)d_in[14];
    const float* sage1_bl = (const float*)d_in[15];
    const float* sage1_wr = (const float*)d_in[16];
    const float* sage2_wl = (const float*)d_in[17];
    const float* sage2_bl = (const float*)d_in[18];
    const float* sage2_wr = (const float*)d_in[19];
    const float* bng_g    = (const float*)d_in[20];
    const float* bng_b    = (const float*)d_in[21];
    const float* bna_g    = (const float*)d_in[22];
    const float* bna_b    = (const float*)d_in[23];
    const float* bns_g    = (const float*)d_in[24];
    const float* bns_b    = (const float*)d_in[25];
    const float* fc1_w    = (const float*)d_in[26];
    const float* fc1_b    = (const float*)d_in[27];
    const float* fc2_w    = (const float*)d_in[28];
    const float* fc2_b    = (const float*)d_in[29];
    float* out = (float*)d_out;

    const int n = in_sizes[0] / 128;
    const int E = in_sizes[1] / 2;
    const int* src = eidx;
    const int* dst = eidx + E;

    float* hg   = symf(d_hg);
    float* g1   = symf(d_g1);
    float* g2   = symf(d_g2);
    float* hgat = symf(d_hgat);
    float* a1   = symf(d_a1);
    float* a2   = symf(d_a2);
    float* hsl  = symf(d_hsl);
    float* hsr  = symf(d_hsr);
    float* s1b  = symf(d_s1);
    float* s2b  = symf(d_s2);
    float* as_  = symf(d_as);
    float* ad_  = symf(d_ad);
    float* dinv = symf(d_dinv);
    int*   cnt  = symi(d_cnt);
    int*   rp   = symi(d_rp);
    int*   cur  = symi(d_cur);
    int*   ci   = symi(d_ci);
    float* bsum = symf(d_bnsum);
    float* bsq  = symf(d_bnsq);
    float* bscale = symf(d_bnscale);
    float* bshift = symf(d_bnshift);

    static cudaStream_t st1 = nullptr, st2 = nullptr;
    static cudaEvent_t evRoot = nullptr, evCSR = nullptr, evGCN = nullptr, evSAGE = nullptr;
    if (!st1){
        cudaStreamCreateWithFlags(&st1, cudaStreamNonBlocking);
        cudaStreamCreateWithFlags(&st2, cudaStreamNonBlocking);
        cudaEventCreateWithFlags(&evRoot, cudaEventDisableTiming);
        cudaEventCreateWithFlags(&evCSR,  cudaEventDisableTiming);
        cudaEventCreateWithFlags(&evGCN,  cudaEventDisableTiming);
        cudaEventCreateWithFlags(&evSAGE, cudaEventDisableTiming);
    }

    const int T = 256;
    auto B  = [](int cnt_){ return dim3(CDIV(cnt_, 256)); };
    auto BW = [n](){ return dim3(CDIV(n*32, 256)); };   // warp per node
    auto GG = [n](int F){ return dim3(CDIV(n,128), F/64); };

    // fork
    cudaEventRecord(evRoot, 0);
    cudaStreamWaitEvent(st1, evRoot, 0);
    cudaStreamWaitEvent(st2, evRoot, 0);

    // ---- st1: CSR build + GCN branch ----
    izero_k   <<<B(n), T, 0, st1>>>(cnt, n);
    hist_k    <<<B(E), T, 0, st1>>>(dst, cnt, E);
    scan_k    <<<1, 1024, 0, st1>>>(cnt, rp, cur, n);
    csr_fill_k<<<B(E), T, 0, st1>>>(src, dst, cur, ci, E);
    dinv_k    <<<B(n), T, 0, st1>>>(cnt, dinv, n);
    cudaEventRecord(evCSR, st1);

    gemm_mma_k  <<<GG(64), T, 0, st1>>>(x, gcn1_w, hg, nullptr, n, 128, 64, 0);
    gcn_gather_k<<<BW(), T, 0, st1>>>(hg, dinv, rp, ci, gcn1_b, g1, n);
    gemm_mma_k  <<<GG(64), T, 0, st1>>>(g1, gcn2_w, hg, nullptr, n, 64, 64, 0);
    gcn_gather_k<<<BW(), T, 0, st1>>>(hg, dinv, rp, ci, gcn2_b, g2, n);
    bn_stats_k  <<<256, T, 0, st1>>>(g2, bsum, bsq, n*64);
    bn_final_k  <<<1, 64, 0, st1>>>(bsum, bsq, bscale, bshift, bng_g, bng_b, n);
    cudaEventRecord(evGCN, st1);

    // ---- st2: SAGE branch ----
    gemm_mma_k<<<GG(64), T, 0, st2>>>(x, sage1_wl, hsl, nullptr, n, 128, 64, 0);
    gemm_mma_k<<<GG(64), T, 0, st2>>>(x, sage1_wr, hsr, nullptr, n, 128, 64, 0);
    cudaStreamWaitEvent(st2, evCSR, 0);
    sage_gather_k<<<BW(), T, 0, st2>>>(hsl, hsr, rp, ci, sage1_bl, s1b, n);
    gemm_mma_k<<<GG(64), T, 0, st2>>>(s1b, sage2_wl, hsl, nullptr, n, 64, 64, 0);
    gemm_mma_k<<<GG(64), T, 0, st2>>>(s1b, sage2_wr, hsr, nullptr, n, 64, 64, 0);
    sage_gather_k<<<BW(), T, 0, st2>>>(hsl, hsr, rp, ci, sage2_bl, s2b, n);
    bn_stats_k<<<256, T, 0, st2>>>(s2b, bsum+128, bsq+128, n*64);
    bn_final_k<<<1, 64, 0, st2>>>(bsum+128, bsq+128, bscale+128, bshift+128, bns_g, bns_b, n);
    cudaEventRecord(evSAGE, st2);

    // ---- main stream: GAT branch (longest) ----
    gemm_mma_k<<<GG(256), T>>>(x, gat1_w, hgat, nullptr, n, 128, 256, 0);
    gat_scal_w_k<<<dim3(CDIV(n*4*32, 256)), T>>>(hgat, gat1_as, gat1_ad, as_, ad_, n, 4);
    cudaStreamWaitEvent(0, evCSR, 0);
    gat1_gather_k<<<BW(), T>>>((const float4*)hgat, (const float4*)as_, (const float4*)ad_,
                               rp, ci, (const float4*)gat1_b, (float4*)a1, n);
    gemm_mma_k<<<GG(64), T>>>(a1, gat2_w, hgat, nullptr, n, 256, 64, 0);
    gat_scal_w_k<<<BW(), T>>>(hgat, gat2_as, gat2_ad, as_, ad_, n, 1);
    gat2_gather_k<<<BW(), T>>>(hgat, as_, ad_, rp, ci, gat2_b, a2, n);
    bn_stats_k<<<256, T>>>(a2, bsum+64, bsq+64, n*64);
    bn_final_k<<<1, 64>>>(bsum+64, bsq+64, bscale+64, bshift+64, bna_g, bna_b, n);

    // join + fused fc1+fc2 head (BN applied on split A-load)
    cudaStreamWaitEvent(0, evGCN, 0);
    cudaStreamWaitEvent(0, evSAGE, 0);
    fc_head_mma_k<<<dim3(CDIV(n,128),1), T>>>(g2, a2, s2b, fc1_w, out,
                                              fc1_b, fc2_w, fc2_b, n, bscale, bshift);
}

// round 17
// speedup vs baseline: 1.0435x; 1.0435x over previous
#include <cuda_runtime.h>
#include <cstdint>
#include <cstdio>

#define NMAX 50000
#define EMAX 600000
#define CDIV(a,b) (((a)+(b)-1)/(b))

// ---------------- scratch (device globals; no allocation allowed) ----------------
__device__ __align__(16) float d_hg  [(size_t)NMAX*64];   // GCN gemm out (dinv-prescaled)
__device__ __align__(16) float d_g1  [(size_t)NMAX*64];
__device__ __align__(16) float d_g2  [(size_t)NMAX*64];
__device__ __align__(16) float d_hgat[(size_t)NMAX*256];  // GAT gemm out
__device__ __align__(16) float d_a1  [(size_t)NMAX*256];
__device__ __align__(16) float d_a2  [(size_t)NMAX*64];
__device__ __align__(16) float d_hsl [(size_t)NMAX*64];   // SAGE x@Wl
__device__ __align__(16) float d_hsr [(size_t)NMAX*64];   // SAGE x@Wr
__device__ __align__(16) float d_s1  [(size_t)NMAX*64];
__device__ __align__(16) float d_s2  [(size_t)NMAX*64];
__device__ __align__(16) float d_as  [(size_t)NMAX*4];
__device__ __align__(16) float d_ad  [(size_t)NMAX*4];
__device__ float d_dinv[NMAX];
__device__ int   d_cnt [NMAX];
__device__ int   d_rp  [NMAX+1];
__device__ int   d_cur [NMAX];
__device__ int   d_ci  [EMAX];
__device__ float d_bnsum[192];   // 3 branches x 64; zero-init, bn_final re-zeroes
__device__ float d_bnsq [192];
__device__ float d_bnscale[192]; // per-channel affine for head A-load
__device__ float d_bnshift[192];

// ---------------- helpers ----------------
__device__ __forceinline__ float lrelu(float x){ return x > 0.f ? x : 0.2f * x; }
__device__ __forceinline__ float elu(float x){ return x > 0.f ? x : expm1f(x); }

__device__ __forceinline__ uint32_t f2tf32(float f){
    uint32_t u;
    asm("cvt.rna.tf32.f32 %0, %1;" : "=r"(u) : "f"(f));
    return u;
}
__device__ __forceinline__ void mma_tf32(float4& d,
    uint32_t a0, uint32_t a1, uint32_t a2, uint32_t a3,
    uint32_t b0, uint32_t b1)
{
    asm volatile(
        "mma.sync.aligned.m16n8k8.row.col.f32.tf32.tf32.f32 "
        "{%0,%1,%2,%3}, {%4,%5,%6,%7}, {%8,%9}, {%0,%1,%2,%3};"
        : "+f"(d.x), "+f"(d.y), "+f"(d.z), "+f"(d.w)
        : "r"(a0), "r"(a1), "r"(a2), "r"(a3), "r"(b0), "r"(b1));
}

// ---------------- CSR build ----------------
__global__ void izero_k(int* p, int n){
    int i = blockIdx.x*blockDim.x + threadIdx.x;
    if (i < n) p[i] = 0;
}
__global__ void hist_k(const int* __restrict__ dst, int* cnt, int E){
    int i = blockIdx.x*blockDim.x + threadIdx.x;
    if (i < E) atomicAdd(&cnt[dst[i]], 1);
}
// single-block scan: rp[0]=0, rp[i+1]=incl sum; cur[i]=exclusive sum; dinv folded in
__global__ void scan_k(const int* __restrict__ cnt, int* rp, int* cur, float* dinv, int n){
    __shared__ int wsum[32];
    __shared__ int carry_s;
    int lane = threadIdx.x & 31, wid = threadIdx.x >> 5;
    if (threadIdx.x == 0){ carry_s = 0; rp[0] = 0; }
    __syncthreads();
    for (int base = 0; base < n; base += 1024){
        int i = base + threadIdx.x;
        int v = (i < n) ? cnt[i] : 0;
        int x = v;
#pragma unroll
        for (int o = 1; o < 32; o <<= 1){
            int t = __shfl_up_sync(0xffffffffu, x, o);
            if (lane >= o) x += t;
        }
        if (lane == 31) wsum[wid] = x;
        __syncthreads();
        if (wid == 0){
            int y = wsum[lane];
#pragma unroll
            for (int o = 1; o < 32; o <<= 1){
                int t = __shfl_up_sync(0xffffffffu, y, o);
                if (lane >= o) y += t;
            }
            wsum[lane] = y;
        }
        __syncthreads();
        int incl = x + (wid > 0 ? wsum[wid-1] : 0) + carry_s;
        if (i < n){
            rp[i+1] = incl;
            cur[i] = incl - v;
            dinv[i] = rsqrtf((float)v + 1.0f);   // +1 self-loop
        }
        __syncthreads();
        if (threadIdx.x == 1023) carry_s = incl;
        __syncthreads();
    }
}
__global__ void csr_fill_k(const int* __restrict__ src, const int* __restrict__ dst,
                           int* cursor, int* ci, int E){
    int e = blockIdx.x*blockDim.x + threadIdx.x;
    if (e < E){
        int p = atomicAdd(&cursor[dst[e]], 1);
        ci[p] = src[e];
    }
}

// ---------------- tf32 tensor-core GEMM ----------------
// C[M,F] = rowscale[m] * (A[M,K] @ B[K,F]) (+bias)(+relu); K%32==0, F%64==0
__global__ __launch_bounds__(256) void gemm_mma_k(
    const float* __restrict__ A, const float* __restrict__ B,
    float* __restrict__ C, const float* __restrict__ bias,
    int M, int K, int F, int act, const float* __restrict__ rowscale)
{
    __shared__ uint32_t As[32][136];
    __shared__ uint32_t Bs[32][72];
    int bm = blockIdx.x * 128;
    int bn = blockIdx.y * 64;
    int tid = threadIdx.x;
    int w = tid >> 5, lane = tid & 31;
    int wm = w & 3, wn = w >> 2;
    int g = lane >> 2, ti = lane & 3;

    float4 acc[2][4];
#pragma unroll
    for (int i=0;i<2;i++)
#pragma unroll
        for (int j=0;j<4;j++) acc[i][j] = make_float4(0.f,0.f,0.f,0.f);

    for (int k0 = 0; k0 < K; k0 += 32){
#pragma unroll
        for (int i=0;i<4;i++){
            int l = tid*4 + i;
            int m = l >> 3, kq = l & 7;
            float4 v = make_float4(0.f,0.f,0.f,0.f);
            if (bm + m < M) v = *(const float4*)&A[(size_t)(bm+m)*K + k0 + kq*4];
            As[kq*4+0][m] = f2tf32(v.x);
            As[kq*4+1][m] = f2tf32(v.y);
            As[kq*4+2][m] = f2tf32(v.z);
            As[kq*4+3][m] = f2tf32(v.w);
        }
#pragma unroll
        for (int i=0;i<2;i++){
            int l = tid*2 + i;
            int kk = l >> 4, nq = l & 15;
            float4 v = *(const float4*)&B[(size_t)(k0+kk)*F + bn + nq*4];
            Bs[kk][nq*4+0] = f2tf32(v.x);
            Bs[kk][nq*4+1] = f2tf32(v.y);
            Bs[kk][nq*4+2] = f2tf32(v.z);
            Bs[kk][nq*4+3] = f2tf32(v.w);
        }
        __syncthreads();
#pragma unroll
        for (int kk = 0; kk < 32; kk += 8){
            uint32_t bf[4][2];
#pragma unroll
            for (int j=0;j<4;j++){
                bf[j][0] = Bs[kk + ti    ][wn*32 + j*8 + g];
                bf[j][1] = Bs[kk + 4 + ti][wn*32 + j*8 + g];
            }
#pragma unroll
            for (int mi=0;mi<2;mi++){
                int mb = wm*32 + mi*16;
                uint32_t a0 = As[kk + ti    ][mb + g];
                uint32_t a1 = As[kk + ti    ][mb + g + 8];
                uint32_t a2 = As[kk + 4 + ti][mb + g];
                uint32_t a3 = As[kk + 4 + ti][mb + g + 8];
#pragma unroll
                for (int j=0;j<4;j++)
                    mma_tf32(acc[mi][j], a0, a1, a2, a3, bf[j][0], bf[j][1]);
            }
        }
        __syncthreads();
    }

#pragma unroll
    for (int mi=0;mi<2;mi++){
#pragma unroll
        for (int j=0;j<4;j++){
            int c = bn + wn*32 + j*8 + 2*ti;
            float b0 = bias ? bias[c]   : 0.f;
            float b1 = bias ? bias[c+1] : 0.f;
            float4 a = acc[mi][j];
            int r0 = bm + wm*32 + mi*16 + g;
            int r1 = r0 + 8;
            float s0 = 1.f, s1 = 1.f;
            if (rowscale){
                if (r0 < M) s0 = rowscale[r0];
                if (r1 < M) s1 = rowscale[r1];
            }
            float2 v0 = make_float2(a.x*s0 + b0, a.y*s0 + b1);
            float2 v1 = make_float2(a.z*s1 + b0, a.w*s1 + b1);
            if (act){
                v0.x = fmaxf(v0.x, 0.f); v0.y = fmaxf(v0.y, 0.f);
                v1.x = fmaxf(v1.x, 0.f); v1.y = fmaxf(v1.y, 0.f);
            }
            if (r0 < M) *(float2*)&C[(size_t)r0*F + c] = v0;
            if (r1 < M) *(float2*)&C[(size_t)r1*F + c] = v1;
        }
    }
}

// fused fc1+fc2 head: out[M,2] = relu(BN(cat)@W1 + b1) @ W2 + b2
__global__ __launch_bounds__(256) void fc_head_mma_k(
    const float* __restrict__ A0, const float* __restrict__ A1, const float* __restrict__ A2,
    const float* __restrict__ B, float* __restrict__ out,
    const float* __restrict__ bias, const float* __restrict__ w2,
    const float* __restrict__ b2,
    int M, const float* __restrict__ ascale, const float* __restrict__ ashift)
{
    const int K = 192, F = 64;
    __shared__ uint32_t As[32][136];
    __shared__ uint32_t Bs[32][72];
    __shared__ float w2s[128];
    __shared__ float part[128][4];
    int bm = blockIdx.x * 128;
    int tid = threadIdx.x;
    int w = tid >> 5, lane = tid & 31;
    int wm = w & 3, wn = w >> 2;
    int g = lane >> 2, ti = lane & 3;

    if (tid < 128) w2s[tid] = w2[tid];

    float4 acc[2][4];
#pragma unroll
    for (int i=0;i<2;i++)
#pragma unroll
        for (int j=0;j<4;j++) acc[i][j] = make_float4(0.f,0.f,0.f,0.f);

    for (int k0 = 0; k0 < K; k0 += 32){
        const float* Ab = (k0 < 64) ? A0 : ((k0 < 128) ? A1 : A2);
        int cb = k0 & 63;
#pragma unroll
        for (int i=0;i<4;i++){
            int l = tid*4 + i;
            int m = l >> 3, kq = l & 7;
            float4 v = make_float4(0.f,0.f,0.f,0.f);
            if (bm + m < M) v = *(const float4*)&Ab[(size_t)(bm+m)*64 + cb + kq*4];
            int c = k0 + kq*4;
            v.x = v.x*ascale[c]   + ashift[c];
            v.y = v.y*ascale[c+1] + ashift[c+1];
            v.z = v.z*ascale[c+2] + ashift[c+2];
            v.w = v.w*ascale[c+3] + ashift[c+3];
            As[kq*4+0][m] = f2tf32(v.x);
            As[kq*4+1][m] = f2tf32(v.y);
            As[kq*4+2][m] = f2tf32(v.z);
            As[kq*4+3][m] = f2tf32(v.w);
        }
#pragma unroll
        for (int i=0;i<2;i++){
            int l = tid*2 + i;
            int kk = l >> 4, nq = l & 15;
            float4 v = *(const float4*)&B[(size_t)(k0+kk)*F + nq*4];
            Bs[kk][nq*4+0] = f2tf32(v.x);
            Bs[kk][nq*4+1] = f2tf32(v.y);
            Bs[kk][nq*4+2] = f2tf32(v.z);
            Bs[kk][nq*4+3] = f2tf32(v.w);
        }
        __syncthreads();
#pragma unroll
        for (int kk = 0; kk < 32; kk += 8){
            uint32_t bf[4][2];
#pragma unroll
            for (int j=0;j<4;j++){
                bf[j][0] = Bs[kk + ti    ][wn*32 + j*8 + g];
                bf[j][1] = Bs[kk + 4 + ti][wn*32 + j*8 + g];
            }
#pragma unroll
            for (int mi=0;mi<2;mi++){
                int mb = wm*32 + mi*16;
                uint32_t a0 = As[kk + ti    ][mb + g];
                uint32_t a1 = As[kk + ti    ][mb + g + 8];
                uint32_t a2 = As[kk + 4 + ti][mb + g];
                uint32_t a3 = As[kk + 4 + ti][mb + g + 8];
#pragma unroll
                for (int j=0;j<4;j++)
                    mma_tf32(acc[mi][j], a0, a1, a2, a3, bf[j][0], bf[j][1]);
            }
        }
        __syncthreads();
    }

    float p[2][2][2];
#pragma unroll
    for (int mi=0;mi<2;mi++)
#pragma unroll
        for (int hf=0;hf<2;hf++){ p[mi][hf][0]=0.f; p[mi][hf][1]=0.f; }

#pragma unroll
    for (int mi=0;mi<2;mi++){
#pragma unroll
        for (int j=0;j<4;j++){
            int c = wn*32 + j*8 + 2*ti;
            float b0 = bias[c], b1 = bias[c+1];
            float4 a = acc[mi][j];
            float v00 = fmaxf(a.x + b0, 0.f), v01 = fmaxf(a.y + b1, 0.f);
            float v10 = fmaxf(a.z + b0, 0.f), v11 = fmaxf(a.w + b1, 0.f);
            float wc0o0 = w2s[c*2+0],   wc0o1 = w2s[c*2+1];
            float wc1o0 = w2s[(c+1)*2], wc1o1 = w2s[(c+1)*2+1];
            p[mi][0][0] += v00*wc0o0 + v01*wc1o0;
            p[mi][0][1] += v00*wc0o1 + v01*wc1o1;
            p[mi][1][0] += v10*wc0o0 + v11*wc1o0;
            p[mi][1][1] += v10*wc0o1 + v11*wc1o1;
        }
    }
#pragma unroll
    for (int mi=0;mi<2;mi++)
#pragma unroll
        for (int hf=0;hf<2;hf++)
#pragma unroll
            for (int o=0;o<2;o++){
                float v = p[mi][hf][o];
                v += __shfl_xor_sync(0xffffffffu, v, 1);
                v += __shfl_xor_sync(0xffffffffu, v, 2);
                p[mi][hf][o] = v;
            }
    if (ti == 0){
#pragma unroll
        for (int mi=0;mi<2;mi++)
#pragma unroll
            for (int hf=0;hf<2;hf++){
                int row = wm*32 + mi*16 + g + hf*8;
                part[row][wn*2+0] = p[mi][hf][0];
                part[row][wn*2+1] = p[mi][hf][1];
            }
    }
    __syncthreads();
    {
        int row = tid >> 1, o = tid & 1;
        int gr = bm + row;
        if (gr < M)
            out[(size_t)gr*2 + o] = part[row][0*2+o] + part[row][1*2+o] + b2[o];
    }
}

// ---------------- fused gather kernels (warp per node, edge-unrolled x2) ----------------
// GCN with dinv-prescaled h': out = relu(dvd*(Σ h'_s + h'_d) + b)
__global__ void gcn_gather_k(const float* __restrict__ h, const float* __restrict__ dinv,
                             const int* __restrict__ rp, const int* __restrict__ ci,
                             const float* __restrict__ bias, float* __restrict__ out, int n)
{
    int w = (blockIdx.x*blockDim.x + threadIdx.x) >> 5;
    if (w >= n) return;
    int lane = threadIdx.x & 31;
    int beg = rp[w], end = rp[w+1];
    float dvd = dinv[w];
    float a0 = h[(size_t)w*64 + lane];
    float a1 = h[(size_t)w*64 + 32 + lane];
    int e = beg;
    for (; e + 2 <= end; e += 2){
        int sA = ci[e], sB = ci[e+1];
        float hA0 = h[(size_t)sA*64 + lane];
        float hA1 = h[(size_t)sA*64 + 32 + lane];
        float hB0 = h[(size_t)sB*64 + lane];
        float hB1 = h[(size_t)sB*64 + 32 + lane];
        a0 += hA0 + hB0;
        a1 += hA1 + hB1;
    }
    if (e < end){
        int s = ci[e];
        a0 += h[(size_t)s*64 + lane];
        a1 += h[(size_t)s*64 + 32 + lane];
    }
    out[(size_t)w*64 + lane]      = fmaxf(dvd*a0 + bias[lane],    0.f);
    out[(size_t)w*64 + 32 + lane] = fmaxf(dvd*a1 + bias[32+lane], 0.f);
}

__global__ void sage_gather_k(const float* __restrict__ hl, const float* __restrict__ xr,
                              const int* __restrict__ rp, const int* __restrict__ ci,
                              const float* __restrict__ bl, float* __restrict__ out, int n)
{
    int w = (blockIdx.x*blockDim.x + threadIdx.x) >> 5;
    if (w >= n) return;
    int lane = threadIdx.x & 31;
    int beg = rp[w], end = rp[w+1];
    float a0 = 0.f, a1 = 0.f;
    int e = beg;
    for (; e + 2 <= end; e += 2){
        int sA = ci[e], sB = ci[e+1];
        float hA0 = hl[(size_t)sA*64 + lane];
        float hA1 = hl[(size_t)sA*64 + 32 + lane];
        float hB0 = hl[(size_t)sB*64 + lane];
        float hB1 = hl[(size_t)sB*64 + 32 + lane];
        a0 += hA0 + hB0;
        a1 += hA1 + hB1;
    }
    if (e < end){
        int s = ci[e];
        a0 += hl[(size_t)s*64 + lane];
        a1 += hl[(size_t)s*64 + 32 + lane];
    }
    float inv = 1.f / fmaxf((float)(end - beg), 1.f);
    out[(size_t)w*64 + lane]      = fmaxf(a0*inv + bl[lane]    + xr[(size_t)w*64 + lane],      0.f);
    out[(size_t)w*64 + 32 + lane] = fmaxf(a1*inv + bl[32+lane] + xr[(size_t)w*64 + 32 + lane], 0.f);
}

// warp per (node,head), C=64: coalesced h reads + shfl reduce.
__global__ __launch_bounds__(256) void gat_scal_w_k(
    const float* __restrict__ h, const float* __restrict__ asrc,
    const float* __restrict__ adst, float* __restrict__ as_, float* __restrict__ ad_,
    int n, int H)
{
    __shared__ float s_as[256], s_ad[256];
    int tid = threadIdx.x;
    int tot = H*64;
    for (int i = tid; i < tot; i += 256){ s_as[i] = asrc[i]; s_ad[i] = adst[i]; }
    __syncthreads();
    int gw = (blockIdx.x*256 + tid) >> 5;   // node*H + head
    if (gw >= n*H) return;
    int lane = tid & 31;
    int node = gw / H, hh = gw - node*H;
    const float* hp = h + (size_t)node*tot + hh*64;
    float v0 = hp[lane], v1 = hp[32+lane];
    float ss = v0*s_as[hh*64+lane] + v1*s_as[hh*64+32+lane];
    float dd = v0*s_ad[hh*64+lane] + v1*s_ad[hh*64+32+lane];
#pragma unroll
    for (int o = 16; o; o >>= 1){
        ss += __shfl_xor_sync(0xffffffffu, ss, o);
        dd += __shfl_xor_sync(0xffffffffu, dd, o);
    }
    if (lane == 0){ as_[gw] = ss; ad_[gw] = dd; }
}

// two-pass GAT1 gather (max pass over L2-resident as4, then weighted pass)
__global__ void gat1_gather_k(const float4* __restrict__ h4, const float4* __restrict__ as4,
                              const float4* __restrict__ ad4,
                              const int* __restrict__ rp, const int* __restrict__ ci,
                              const float4* __restrict__ bias4, float4* __restrict__ out4, int n)
{
    int w = (blockIdx.x*blockDim.x + threadIdx.x) >> 5;
    if (w >= n) return;
    int lane = threadIdx.x & 31;
    bool lo = (lane < 16);
    int beg = rp[w], end = rp[w+1];
    float4 ad = ad4[w];
    float adv0 = lo ? ad.x : ad.y;
    float adv1 = lo ? ad.z : ad.w;
    float4 asw = as4[w];
    float es0 = lrelu((lo ? asw.x : asw.y) + adv0);
    float es1 = lrelu((lo ? asw.z : asw.w) + adv1);
    float m0 = es0, m1 = es1;
    {
        int e = beg;
        for (; e + 2 <= end; e += 2){
            float4 a = as4[ci[e]];
            float4 b = as4[ci[e+1]];
            m0 = fmaxf(m0, fmaxf(lrelu((lo ? a.x : a.y) + adv0),
                                 lrelu((lo ? b.x : b.y) + adv0)));
            m1 = fmaxf(m1, fmaxf(lrelu((lo ? a.z : a.w) + adv1),
                                 lrelu((lo ? b.z : b.w) + adv1)));
        }
        if (e < end){
            float4 a = as4[ci[e]];
            m0 = fmaxf(m0, lrelu((lo ? a.x : a.y) + adv0));
            m1 = fmaxf(m1, lrelu((lo ? a.z : a.w) + adv1));
        }
    }
    float w0 = expf(es0 - m0), w1 = expf(es1 - m1);
    float den0 = w0, den1 = w1;
    float4 hv0 = h4[(size_t)w*64 + lane];
    float4 hv1 = h4[(size_t)w*64 + 32 + lane];
    float4 acc0 = make_float4(w0*hv0.x, w0*hv0.y, w0*hv0.z, w0*hv0.w);
    float4 acc1 = make_float4(w1*hv1.x, w1*hv1.y, w1*hv1.z, w1*hv1.w);
    int e = beg;
    for (; e + 2 <= end; e += 2){
        int sA = ci[e], sB = ci[e+1];
        float4 aA = as4[sA];
        float4 aB = as4[sB];
        float wA0 = expf(lrelu((lo ? aA.x : aA.y) + adv0) - m0);
        float wA1 = expf(lrelu((lo ? aA.z : aA.w) + adv1) - m1);
        float wB0 = expf(lrelu((lo ? aB.x : aB.y) + adv0) - m0);
        float wB1 = expf(lrelu((lo ? aB.z : aB.w) + adv1) - m1);
        den0 += wA0 + wB0; den1 += wA1 + wB1;
        float4 vA0 = h4[(size_t)sA*64 + lane];
        float4 vA1 = h4[(size_t)sA*64 + 32 + lane];
        float4 vB0 = h4[(size_t)sB*64 + lane];
        float4 vB1 = h4[(size_t)sB*64 + 32 + lane];
        acc0.x += wA0*vA0.x + wB0*vB0.x; acc0.y += wA0*vA0.y + wB0*vB0.y;
        acc0.z += wA0*vA0.z + wB0*vB0.z; acc0.w += wA0*vA0.w + wB0*vB0.w;
        acc1.x += wA1*vA1.x + wB1*vB1.x; acc1.y += wA1*vA1.y + wB1*vB1.y;
        acc1.z += wA1*vA1.z + wB1*vB1.z; acc1.w += wA1*vA1.w + wB1*vB1.w;
    }
    if (e < end){
        int s = ci[e];
        float4 a = as4[s];
        float we0 = expf(lrelu((lo ? a.x : a.y) + adv0) - m0);
        float we1 = expf(lrelu((lo ? a.z : a.w) + adv1) - m1);
        den0 += we0; den1 += we1;
        float4 v0 = h4[(size_t)s*64 + lane];
        float4 v1 = h4[(size_t)s*64 + 32 + lane];
        acc0.x += we0*v0.x; acc0.y += we0*v0.y; acc0.z += we0*v0.z; acc0.w += we0*v0.w;
        acc1.x += we1*v1.x; acc1.y += we1*v1.y; acc1.z += we1*v1.z; acc1.w += we1*v1.w;
    }
    float inv0 = 1.f/(den0 + 1e-16f), inv1 = 1.f/(den1 + 1e-16f);
    float4 b0 = bias4[lane], b1 = bias4[32+lane];
    float4 o0, o1;
    o0.x = elu(acc0.x*inv0 + b0.x); o0.y = elu(acc0.y*inv0 + b0.y);
    o0.z = elu(acc0.z*inv0 + b0.z); o0.w = elu(acc0.w*inv0 + b0.w);
    o1.x = elu(acc1.x*inv1 + b1.x); o1.y = elu(acc1.y*inv1 + b1.y);
    o1.z = elu(acc1.z*inv1 + b1.z); o1.w = elu(acc1.w*inv1 + b1.w);
    out4[(size_t)w*64 + lane] = o0;
    out4[(size_t)w*64 + 32 + lane] = o1;
}

// two-pass GAT2 gather
__global__ void gat2_gather_k(const float* __restrict__ h, const float* __restrict__ as_,
                              const float* __restrict__ ad_,
                              const int* __restrict__ rp, const int* __restrict__ ci,
                              const float* __restrict__ bias, float* __restrict__ out, int n)
{
    int w = (blockIdx.x*blockDim.x + threadIdx.x) >> 5;
    if (w >= n) return;
    int lane = threadIdx.x & 31;
    int beg = rp[w], end = rp[w+1];
    float adv = ad_[w];
    float es = lrelu(as_[w] + adv);
    float m = es;
    {
        int e = beg;
        for (; e + 2 <= end; e += 2){
            float eA = lrelu(as_[ci[e]]   + adv);
            float eB = lrelu(as_[ci[e+1]] + adv);
            m = fmaxf(m, fmaxf(eA, eB));
        }
        if (e < end) m = fmaxf(m, lrelu(as_[ci[e]] + adv));
    }
    float w0 = expf(es - m);
    float den = w0;
    float a0 = w0 * h[(size_t)w*64 + lane];
    float a1 = w0 * h[(size_t)w*64 + 32 + lane];
    int e = beg;
    for (; e + 2 <= end; e += 2){
        int sA = ci[e], sB = ci[e+1];
        float wA = expf(lrelu(as_[sA] + adv) - m);
        float wB = expf(lrelu(as_[sB] + adv) - m);
        float hA0 = h[(size_t)sA*64 + lane];
        float hA1 = h[(size_t)sA*64 + 32 + lane];
        float hB0 = h[(size_t)sB*64 + lane];
        float hB1 = h[(size_t)sB*64 + 32 + lane];
        den += wA + wB;
        a0 += wA*hA0 + wB*hB0;
        a1 += wA*hA1 + wB*hB1;
    }
    if (e < end){
        int s = ci[e];
        float we = expf(lrelu(as_[s] + adv) - m);
        den += we;
        a0 += we * h[(size_t)s*64 + lane];
        a1 += we * h[(size_t)s*64 + 32 + lane];
    }
    float inv = 1.f/(den + 1e-16f);
    out[(size_t)w*64 + lane]      = elu(a0*inv + bias[lane]);
    out[(size_t)w*64 + 32 + lane] = elu(a1*inv + bias[32+lane]);
}

// ---------------- BatchNorm ----------------
__global__ void bn_stats_k(const float* __restrict__ x, float* gsum, float* gsq, int total){
    __shared__ float ss[256];
    __shared__ float sq[256];
    int tid = threadIdx.x;
    float s = 0.f, q = 0.f;
    for (int i = blockIdx.x*256 + tid; i < total; i += gridDim.x*256){
        float v = x[i];
        s += v; q += v*v;
    }
    ss[tid] = s; sq[tid] = q;
    __syncthreads();
    if (tid < 64){
        int c = tid & 63;
        float ts = ss[tid] + ss[tid+64] + ss[tid+128] + ss[tid+192];
        float tq = sq[tid] + sq[tid+64] + sq[tid+128] + sq[tid+192];
        atomicAdd(&gsum[c], ts);
        atomicAdd(&gsq[c], tq);
    }
}
__global__ void bn_final_k(float* gsum, float* gsq, float* scale, float* shift,
                           const float* __restrict__ g, const float* __restrict__ b, int n){
    int c = threadIdx.x;
    if (c < 64){
        float m = gsum[c] / (float)n;
        float v = gsq[c] / (float)n - m*m;
        float sc = g[c] * rsqrtf(v + 1e-5f);
        scale[c] = sc;
        shift[c] = b[c] - m*sc;
        gsum[c] = 0.f;
        gsq[c]  = 0.f;
    }
}

// ---------------- host orchestration ----------------
static inline float* symf(const void* s){ void* p=nullptr; cudaGetSymbolAddress(&p, s); return (float*)p; }
static inline int*   symi(const void* s){ void* p=nullptr; cudaGetSymbolAddress(&p, s); return (int*)p; }

extern "C" void kernel_launch(void* const* d_in, const int* in_sizes, int n_in,
                              void* d_out, int out_size)
{
    const float* x        = (const float*)d_in[0];
    const int*   eidx     = (const int*)  d_in[1];
    const float* gcn1_w   = (const float*)d_in[2];
    const float* gcn1_b   = (const float*)d_in[3];
    const float* gcn2_w   = (const float*)d_in[4];
    const float* gcn2_b   = (const float*)d_in[5];
    const float* gat1_w   = (const float*)d_in[6];
    const float* gat1_as  = (const float*)d_in[7];
    const float* gat1_ad  = (const float*)d_in[8];
    const float* gat1_b   = (const float*)d_in[9];
    const float* gat2_w   = (const float*)d_in[10];
    const float* gat2_as  = (const float*)d_in[11];
    const float* gat2_ad  = (const float*)d_in[12];
    const float* gat2_b   = (const float*)d_in[13];
    const float* sage1_wl = (const float*)d_in[14];
    const float* sage1_bl = (const float*)d_in[15];
    const float* sage1_wr = (const float*)d_in[16];
    const float* sage2_wl = (const float*)d_in[17];
    const float* sage2_bl = (const float*)d_in[18];
    const float* sage2_wr = (const float*)d_in[19];
    const float* bng_g    = (const float*)d_in[20];
    const float* bng_b    = (const float*)d_in[21];
    const float* bna_g    = (const float*)d_in[22];
    const float* bna_b    = (const float*)d_in[23];
    const float* bns_g    = (const float*)d_in[24];
    const float* bns_b    = (const float*)d_in[25];
    const float* fc1_w    = (const float*)d_in[26];
    const float* fc1_b    = (const float*)d_in[27];
    const float* fc2_w    = (const float*)d_in[28];
    const float* fc2_b    = (const float*)d_in[29];
    float* out = (float*)d_out;

    const int n = in_sizes[0] / 128;
    const int E = in_sizes[1] / 2;
    const int* src = eidx;
    const int* dst = eidx + E;

    float* hg   = symf(d_hg);
    float* g1   = symf(d_g1);
    float* g2   = symf(d_g2);
    float* hgat = symf(d_hgat);
    float* a1   = symf(d_a1);
    float* a2   = symf(d_a2);
    float* hsl  = symf(d_hsl);
    float* hsr  = symf(d_hsr);
    float* s1b  = symf(d_s1);
    float* s2b  = symf(d_s2);
    float* as_  = symf(d_as);
    float* ad_  = symf(d_ad);
    float* dinv = symf(d_dinv);
    int*   cnt  = symi(d_cnt);
    int*   rp   = symi(d_rp);
    int*   cur  = symi(d_cur);
    int*   ci   = symi(d_ci);
    float* bsum = symf(d_bnsum);
    float* bsq  = symf(d_bnsq);
    float* bscale = symf(d_bnscale);
    float* bshift = symf(d_bnshift);

    static cudaStream_t st1 = nullptr, st2 = nullptr;
    static cudaEvent_t evRoot = nullptr, evCSR = nullptr, evGCN = nullptr, evSAGE = nullptr;
    if (!st1){
        cudaStreamCreateWithFlags(&st1, cudaStreamNonBlocking);
        cudaStreamCreateWithFlags(&st2, cudaStreamNonBlocking);
        cudaEventCreateWithFlags(&evRoot, cudaEventDisableTiming);
        cudaEventCreateWithFlags(&evCSR,  cudaEventDisableTiming);
        cudaEventCreateWithFlags(&evGCN,  cudaEventDisableTiming);
        cudaEventCreateWithFlags(&evSAGE, cudaEventDisableTiming);
    }

    const int T = 256;
    auto B  = [](int cnt_){ return dim3(CDIV(cnt_, 256)); };
    auto BW = [n](){ return dim3(CDIV(n*32, 256)); };   // warp per node
    auto GG = [n](int F){ return dim3(CDIV(n,128), F/64); };

    // fork
    cudaEventRecord(evRoot, 0);
    cudaStreamWaitEvent(st1, evRoot, 0);
    cudaStreamWaitEvent(st2, evRoot, 0);

    // ---- st1: CSR build + GCN branch ----
    izero_k   <<<B(n), T, 0, st1>>>(cnt, n);
    hist_k    <<<B(E), T, 0, st1>>>(dst, cnt, E);
    scan_k    <<<1, 1024, 0, st1>>>(cnt, rp, cur, dinv, n);
    csr_fill_k<<<B(E), T, 0, st1>>>(src, dst, cur, ci, E);
    cudaEventRecord(evCSR, st1);

    gemm_mma_k  <<<GG(64), T, 0, st1>>>(x, gcn1_w, hg, nullptr, n, 128, 64, 0, dinv);
    gcn_gather_k<<<BW(), T, 0, st1>>>(hg, dinv, rp, ci, gcn1_b, g1, n);
    gemm_mma_k  <<<GG(64), T, 0, st1>>>(g1, gcn2_w, hg, nullptr, n, 64, 64, 0, dinv);
    gcn_gather_k<<<BW(), T, 0, st1>>>(hg, dinv, rp, ci, gcn2_b, g2, n);
    bn_stats_k  <<<256, T, 0, st1>>>(g2, bsum, bsq, n*64);
    bn_final_k  <<<1, 64, 0, st1>>>(bsum, bsq, bscale, bshift, bng_g, bng_b, n);
    cudaEventRecord(evGCN, st1);

    // ---- st2: SAGE branch ----
    gemm_mma_k<<<GG(64), T, 0, st2>>>(x, sage1_wl, hsl, nullptr, n, 128, 64, 0, nullptr);
    gemm_mma_k<<<GG(64), T, 0, st2>>>(x, sage1_wr, hsr, nullptr, n, 128, 64, 0, nullptr);
    cudaStreamWaitEvent(st2, evCSR, 0);
    sage_gather_k<<<BW(), T, 0, st2>>>(hsl, hsr, rp, ci, sage1_bl, s1b, n);
    gemm_mma_k<<<GG(64), T, 0, st2>>>(s1b, sage2_wl, hsl, nullptr, n, 64, 64, 0, nullptr);
    gemm_mma_k<<<GG(64), T, 0, st2>>>(s1b, sage2_wr, hsr, nullptr, n, 64, 64, 0, nullptr);
    sage_gather_k<<<BW(), T, 0, st2>>>(hsl, hsr, rp, ci, sage2_bl, s2b, n);
    bn_stats_k<<<256, T, 0, st2>>>(s2b, bsum+128, bsq+128, n*64);
    bn_final_k<<<1, 64, 0, st2>>>(bsum+128, bsq+128, bscale+128, bshift+128, bns_g, bns_b, n);
    cudaEventRecord(evSAGE, st2);

    // ---- main stream: GAT branch (longest) ----
    gemm_mma_k<<<GG(256), T>>>(x, gat1_w, hgat, nullptr, n, 128, 256, 0, nullptr);
    gat_scal_w_k<<<dim3(CDIV(n*4*32, 256)), T>>>(hgat, gat1_as, gat1_ad, as_, ad_, n, 4);
    cudaStreamWaitEvent(0, evCSR, 0);
    gat1_gather_k<<<BW(), T>>>((const float4*)hgat, (const float4*)as_, (const float4*)ad_,
                               rp, ci, (const float4*)gat1_b, (float4*)a1, n);
    gemm_mma_k<<<GG(64), T>>>(a1, gat2_w, hgat, nullptr, n, 256, 64, 0, nullptr);
    gat_scal_w_k<<<BW(), T>>>(hgat, gat2_as, gat2_ad, as_, ad_, n, 1);
    gat2_gather_k<<<BW(), T>>>(hgat, as_, ad_, rp, ci, gat2_b, a2, n);
    bn_stats_k<<<256, T>>>(a2, bsum+64, bsq+64, n*64);
    bn_final_k<<<1, 64>>>(bsum+64, bsq+64, bscale+64, bshift+64, bna_g, bna_b, n);

    // join + fused fc1+fc2 head (BN applied on split A-load)
    cudaStreamWaitEvent(0, evGCN, 0);
    cudaStreamWaitEvent(0, evSAGE, 0);
    fc_head_mma_k<<<dim3(CDIV(n,128),1), T>>>(g2, a2, s2b, fc1_w, out,
                                              fc1_b, fc2_w, fc2_b, n, bscale, bshift);
}